// round 2
// baseline (speedup 1.0000x reference)
#include <cuda_runtime.h>
#include <math.h>

// ---------------- constants ----------------
#define NIMG 8
#define NUM_CLASSES 80
#define LCH 85            // 5 + NUM_CLASSES
#define IMGF 640.0f
#define SCORE_T 0.1f
#define NMS_T 0.6f
#define DET 100
#define OBJ_CAP 32768     // global obj-pass candidate cap (expected ~300)
#define DCAP 4096         // per-image detection candidate cap (expected ~0-40)
#define SORT_N 4096       // pow2 >= DCAP
#define TOPK 1000

__constant__ float2 c_anchors[3][3] = {
    {{6.1f, 8.1f}, {20.6f, 12.6f}, {11.2f, 23.7f}},
    {{36.2f, 26.8f}, {25.9f, 57.2f}, {57.8f, 47.9f}},
    {{122.1f, 78.3f}, {73.7f, 143.8f}, {236.1f, 213.1f}},
};

// counters[0] = obj candidate count, counters[1+n] = detection count for image n
__device__ int g_counters[9];
__device__ int g_objCand[OBJ_CAP];                 // packed: n<<17 | level<<15 | a<<13 | hw
__device__ float  g_detScore[NIMG][DCAP];
__device__ float4 g_detBox[NIMG][DCAP];            // clipped xyxy
__device__ int    g_detInfo[NIMG][DCAP];           // topi = anchor_global*80 + label

__device__ __forceinline__ float sigf(float x) { return 1.0f / (1.0f + expf(-x)); }

// ------------- pass 1: objectness-only GEMM (3 outputs per location) -------------
__global__ void obj_kernel(const float* __restrict__ f, const float* __restrict__ w,
                           const float* __restrict__ b, int C, int HW, int level, int total)
{
    __shared__ float sw[3 * 512];
    __shared__ float sb[3];
    for (int i = threadIdx.x; i < 3 * C; i += blockDim.x) {
        int a = i / C, c = i - a * C;
        sw[i] = w[(a * LCH + 4) * C + c];
    }
    if (threadIdx.x < 3) sb[threadIdx.x] = b[threadIdx.x * LCH + 4];
    __syncthreads();

    int id = blockIdx.x * blockDim.x + threadIdx.x;
    if (id >= total) return;
    int n = id / HW, hw = id - n * HW;
    const float* fp = f + (size_t)n * C * HW + hw;

    float a0 = sb[0], a1 = sb[1], a2 = sb[2];
    const float* sw1 = sw + C;
    const float* sw2 = sw + 2 * C;
#pragma unroll 8
    for (int c = 0; c < C; c++) {
        float v = __ldg(fp + (size_t)c * HW);
        a0 = fmaf(v, sw[c],  a0);
        a1 = fmaf(v, sw1[c], a1);
        a2 = fmaf(v, sw2[c], a2);
    }
    float lg[3] = {a0, a1, a2};
#pragma unroll
    for (int a = 0; a < 3; a++) {
        if (sigf(lg[a]) > SCORE_T) {
            int idx = atomicAdd(&g_counters[0], 1);
            if (idx < OBJ_CAP)
                g_objCand[idx] = (n << 17) | (level << 15) | (a << 13) | hw;
        }
    }
}

// ------------- pass 2: full 85-channel head only for obj-passing anchors -------------
__global__ void cand_kernel(const float* __restrict__ f0, const float* __restrict__ f1,
                            const float* __restrict__ f2,
                            const float* __restrict__ w0, const float* __restrict__ w1,
                            const float* __restrict__ w2,
                            const float* __restrict__ b0, const float* __restrict__ b1,
                            const float* __restrict__ b2)
{
    __shared__ float shf[512];
    __shared__ float lg[LCH];
    __shared__ float4 s_box;
    __shared__ float s_obj;

    int total = g_counters[0];
    if (total > OBJ_CAP) total = OBJ_CAP;

    for (int ci = blockIdx.x; ci < total; ci += gridDim.x) {
        int pk = g_objCand[ci];
        int n = pk >> 17, level = (pk >> 15) & 3, a = (pk >> 13) & 3, hw = pk & 0x1FFF;

        const float *f, *w, *b;
        int C, HW, W, aoff;
        float stride;
        if (level == 0)      { f = f0; w = w0; b = b0; C = 128; HW = 6400; W = 80; stride = 8.f;  aoff = 0; }
        else if (level == 1) { f = f1; w = w1; b = b1; C = 256; HW = 1600; W = 40; stride = 16.f; aoff = 19200; }
        else                 { f = f2; w = w2; b = b2; C = 512; HW = 400;  W = 20; stride = 32.f; aoff = 24000; }

        for (int c = threadIdx.x; c < C; c += blockDim.x)
            shf[c] = f[((size_t)n * C + c) * HW + hw];
        __syncthreads();

        int t = threadIdx.x;
        if (t < LCH) {
            int row = a * LCH + t;
            const float* wr = w + (size_t)row * C;
            float acc = b[row];
            for (int c = 0; c < C; c++) acc = fmaf(shf[c], wr[c], acc);
            lg[t] = acc;
        }
        __syncthreads();

        if (t == 0) {
            float px = sigf(lg[0]), py = sigf(lg[1]);
            float pw = sigf(lg[2]), ph = sigf(lg[3]);
            s_obj = sigf(lg[4]);
            int gx = hw % W, gy = hw / W;
            float2 anc = c_anchors[level][a];
            float cx = (2.f * px - 0.5f + (float)gx) * stride;
            float cy = (2.f * py - 0.5f + (float)gy) * stride;
            float bw = 4.f * pw * pw * anc.x;
            float bh = 4.f * ph * ph * anc.y;
            float x1 = cx - 0.5f * bw, y1 = cy - 0.5f * bh;
            float x2 = cx + 0.5f * bw, y2 = cy + 0.5f * bh;
            x1 = fminf(fmaxf(x1, 0.f), IMGF);
            y1 = fminf(fmaxf(y1, 0.f), IMGF);
            x2 = fminf(fmaxf(x2, 0.f), IMGF);
            y2 = fminf(fmaxf(y2, 0.f), IMGF);
            s_box = make_float4(x1, y1, x2, y2);
        }
        __syncthreads();

        if (t < NUM_CLASSES) {
            float ob = s_obj;
            if (ob > SCORE_T) {
                float s = ob * sigf(lg[5 + t]);
                if (s > SCORE_T) {
                    int pos = atomicAdd(&g_counters[1 + n], 1);
                    if (pos < DCAP) {
                        g_detScore[n][pos] = s;
                        g_detBox[n][pos]   = s_box;
                        g_detInfo[n][pos]  = (aoff + hw * 3 + a) * NUM_CLASSES + t;
                    }
                }
            }
        }
        __syncthreads();
    }
}

// ------------- pass 3: per-image sort (top_k semantics) + greedy NMS + output -------------
__global__ void nms_kernel(const float* __restrict__ sf, float* __restrict__ out)
{
    extern __shared__ char smem[];
    unsigned long long* keys = (unsigned long long*)smem;                 // SORT_N * 8
    int*    payload = (int*)   (smem + SORT_N * 8);                       // SORT_N * 4
    float4* box     = (float4*)(smem + SORT_N * 12);                      // 1024 * 16
    float*  scr     = (float*) (smem + SORT_N * 12 + 1024 * 16);          // 1024 * 4
    int*    lab     = (int*)   (smem + SORT_N * 12 + 1024 * 20);          // 1024 * 4
    int*    val     = (int*)   (smem + SORT_N * 12 + 1024 * 24);          // 1024 * 4
    int*    picks   = (int*)   (smem + SORT_N * 12 + 1024 * 28);          // DET * 4
    __shared__ int s_sel, s_np;

    int n = blockIdx.x;
    int tid = threadIdx.x;
    int M = g_counters[1 + n];
    if (M > DCAP) M = DCAP;

    // build sort keys: (orderable(score) desc, topi asc) — replicates lax.top_k ordering
    for (int i = tid; i < SORT_N; i += blockDim.x) {
        if (i < M) {
            unsigned u = __float_as_uint(g_detScore[n][i]);
            u = (u & 0x80000000u) ? ~u : (u | 0x80000000u);
            keys[i] = ((unsigned long long)u << 32) | (unsigned)(0x7FFFFFFF - g_detInfo[n][i]);
            payload[i] = i;
        } else {
            keys[i] = 0ULL;
            payload[i] = -1;
        }
    }
    if (tid == 0) s_np = 0;
    __syncthreads();

    // bitonic sort, descending
    for (int k = 2; k <= SORT_N; k <<= 1) {
        for (int j = k >> 1; j > 0; j >>= 1) {
            for (int i = tid; i < SORT_N; i += blockDim.x) {
                int ixj = i ^ j;
                if (ixj > i) {
                    bool up = ((i & k) == 0);
                    unsigned long long ka = keys[i], kb = keys[ixj];
                    bool sw = up ? (ka < kb) : (ka > kb);
                    if (sw) {
                        keys[i] = kb; keys[ixj] = ka;
                        int p = payload[i]; payload[i] = payload[ixj]; payload[ixj] = p;
                    }
                }
            }
            __syncthreads();
        }
    }

    int M2 = M < TOPK ? M : TOPK;   // top-1000 cap
    for (int i = tid; i < M2; i += blockDim.x) {
        int ci = payload[i];
        box[i] = g_detBox[n][ci];
        scr[i] = g_detScore[n][ci];
        lab[i] = g_detInfo[n][ci] % NUM_CLASSES;
        val[i] = 1;
    }
    __syncthreads();

    // greedy NMS in score-descending order (== argmax loop for distinct scores,
    // tie order matched via sort's secondary key). Class offset => same-label only.
    int cursor = 0;  // only meaningful in tid 0
    for (int iter = 0; iter < DET; iter++) {
        if (tid == 0) {
            int sel = -1;
            for (int j = cursor; j < M2; j++)
                if (val[j]) { sel = j; break; }
            s_sel = sel;
            if (sel >= 0) {
                picks[iter] = sel;
                val[sel] = 0;
                s_np = iter + 1;
                cursor = sel + 1;
            }
        }
        __syncthreads();
        int sel = s_sel;
        if (sel < 0) break;
        float4 bs = box[sel];
        int ls = lab[sel];
        float areaS = (bs.z - bs.x) * (bs.w - bs.y);
        for (int j = tid; j < M2; j += blockDim.x) {
            if (val[j] && lab[j] == ls) {
                float4 bj = box[j];
                float ix1 = fmaxf(bs.x, bj.x), iy1 = fmaxf(bs.y, bj.y);
                float ix2 = fminf(bs.z, bj.z), iy2 = fminf(bs.w, bj.w);
                float iw = fmaxf(ix2 - ix1, 0.f), ih = fmaxf(iy2 - iy1, 0.f);
                float inter = iw * ih;
                float aj = (bj.z - bj.x) * (bj.w - bj.y);
                float iou = inter / (areaS + aj - inter + 1e-7f);
                if (iou > NMS_T) val[j] = 0;
            }
        }
        __syncthreads();
    }
    __syncthreads();

    int np = s_np;
    float s = sf[n];
    for (int d = tid; d < DET; d += blockDim.x) {
        float o0 = 0, o1 = 0, o2 = 0, o3 = 0, o4 = 0, o5 = 0;
        if (d < np) {
            int p = picks[d];
            float4 bb = box[p];
            o0 = bb.x / s; o1 = bb.y / s; o2 = bb.z / s; o3 = bb.w / s;
            o4 = scr[p];
            o5 = (float)lab[p];
        }
        float* po = out + ((size_t)n * DET + d) * 6;
        po[0] = o0; po[1] = o1; po[2] = o2; po[3] = o3; po[4] = o4; po[5] = o5;
    }
}

// ---------------- launch ----------------
extern "C" void kernel_launch(void* const* d_in, const int* in_sizes, int n_in,
                              void* d_out, int out_size)
{
    // Resolve inputs by element count (robust to metadata ordering).
    // f0: 8*128*80*80 = 6553600   w0: 255*128 = 32640
    // f1: 8*256*40*40 = 3276800   w1: 255*256 = 65280
    // f2: 8*512*20*20 = 1638400   w2: 255*512 = 130560
    // b0,b1,b2: 255 each (assigned in encounter order)   sf: 8
    const float *f0 = nullptr, *f1 = nullptr, *f2 = nullptr;
    const float *w0 = nullptr, *w1 = nullptr, *w2 = nullptr;
    const float *bb[3] = {nullptr, nullptr, nullptr};
    const float *sf = nullptr;
    int bcount = 0;
    for (int i = 0; i < n_in; i++) {
        const float* p = (const float*)d_in[i];
        switch (in_sizes[i]) {
            case 6553600: f0 = p; break;
            case 3276800: f1 = p; break;
            case 1638400: f2 = p; break;
            case 32640:   w0 = p; break;
            case 65280:   w1 = p; break;
            case 130560:  w2 = p; break;
            case 255:     if (bcount < 3) bb[bcount++] = p; break;
            case 8:       sf = p; break;
            default: break;
        }
    }
    const float *b0 = bb[0], *b1 = bb[1], *b2 = bb[2];
    float* out = (float*)d_out;

    void* caddr = nullptr;
    cudaGetSymbolAddress(&caddr, g_counters);
    cudaMemsetAsync(caddr, 0, 9 * sizeof(int), 0);

    obj_kernel<<<(NIMG * 6400 + 255) / 256, 256>>>(f0, w0, b0, 128, 6400, 0, NIMG * 6400);
    obj_kernel<<<(NIMG * 1600 + 255) / 256, 256>>>(f1, w1, b1, 256, 1600, 1, NIMG * 1600);
    obj_kernel<<<(NIMG * 400  + 255) / 256, 256>>>(f2, w2, b2, 512, 400,  2, NIMG * 400);

    cand_kernel<<<296, 128>>>(f0, f1, f2, w0, w1, w2, b0, b1, b2);

    cudaFuncSetAttribute(nms_kernel, cudaFuncAttributeMaxDynamicSharedMemorySize, 78336);
    nms_kernel<<<NIMG, 1024, 78336>>>(sf, out);
}

// round 3
// speedup vs baseline: 2.5778x; 2.5778x over previous
#include <cuda_runtime.h>
#include <math.h>

// ---------------- constants ----------------
#define NIMG 8
#define NUM_CLASSES 80
#define LCH 85            // 5 + NUM_CLASSES
#define IMGF 640.0f
#define SCORE_T 0.1f
#define NMS_T 0.6f
#define DET 100
#define OBJ_CAP 32768
#define DCAP 4096
#define SORT_N 4096
#define TOPK 1000

// logit(0.1) = -2.197224577; conservative margin — exact sigmoid recheck happens in cand_kernel
#define OBJ_LOGIT_T (-2.199224577f)

__constant__ float2 c_anchors[3][3] = {
    {{6.1f, 8.1f}, {20.6f, 12.6f}, {11.2f, 23.7f}},
    {{36.2f, 26.8f}, {25.9f, 57.2f}, {57.8f, 47.9f}},
    {{122.1f, 78.3f}, {73.7f, 143.8f}, {236.1f, 213.1f}},
};

__device__ int g_counters[9];                      // [0]=obj count, [1+n]=det count
__device__ int g_objCand[OBJ_CAP];                 // n<<17 | level<<15 | a<<13 | hw
__device__ float  g_detScore[NIMG][DCAP];
__device__ float4 g_detBox[NIMG][DCAP];
__device__ int    g_detInfo[NIMG][DCAP];

__device__ __forceinline__ float sigf(float x) { return 1.0f / (1.0f + expf(-x)); }

// ------------- pass 1: fused objectness-only GEMV, all 3 levels, float4 over hw -------------
// grid layout: blocks [0,50) -> level0, [50,63) -> level1, [63,67) -> level2, 256 thr
#define L0_BLK 50
#define L1_BLK 13
#define L2_BLK 4

__global__ void obj_kernel(const float* __restrict__ f0, const float* __restrict__ f1,
                           const float* __restrict__ f2,
                           const float* __restrict__ w0, const float* __restrict__ w1,
                           const float* __restrict__ w2,
                           const float* __restrict__ b0, const float* __restrict__ b1,
                           const float* __restrict__ b2)
{
    __shared__ float sw[3 * 512];
    __shared__ float sb[3];

    int blk = blockIdx.x;
    const float *f, *w, *b;
    int C, HW, level, blk0;
    if (blk < L0_BLK)               { f = f0; w = w0; b = b0; C = 128; HW = 6400; level = 0; blk0 = 0; }
    else if (blk < L0_BLK + L1_BLK) { f = f1; w = w1; b = b1; C = 256; HW = 1600; level = 1; blk0 = L0_BLK; }
    else                            { f = f2; w = w2; b = b2; C = 512; HW = 400;  level = 2; blk0 = L0_BLK + L1_BLK; }

    for (int i = threadIdx.x; i < 3 * C; i += blockDim.x) {
        int a = i / C, c = i - a * C;
        sw[i] = w[(a * LCH + 4) * C + c];
    }
    if (threadIdx.x < 3) sb[threadIdx.x] = b[threadIdx.x * LCH + 4];
    __syncthreads();

    int HW4 = HW >> 2;
    int total4 = NIMG * HW4;
    int id = (blk - blk0) * blockDim.x + threadIdx.x;
    if (id >= total4) return;
    int n = id / HW4, q = id - n * HW4;

    const float4* fb = (const float4*)f + (size_t)n * C * HW4 + q;

    float4 a0 = make_float4(sb[0], sb[0], sb[0], sb[0]);
    float4 a1 = make_float4(sb[1], sb[1], sb[1], sb[1]);
    float4 a2 = make_float4(sb[2], sb[2], sb[2], sb[2]);
    const float* sw1 = sw + C;
    const float* sw2 = sw + 2 * C;

#pragma unroll 8
    for (int c = 0; c < C; c++) {
        float4 v = __ldg(fb + (size_t)c * HW4);
        float w0v = sw[c], w1v = sw1[c], w2v = sw2[c];
        a0.x = fmaf(v.x, w0v, a0.x); a0.y = fmaf(v.y, w0v, a0.y);
        a0.z = fmaf(v.z, w0v, a0.z); a0.w = fmaf(v.w, w0v, a0.w);
        a1.x = fmaf(v.x, w1v, a1.x); a1.y = fmaf(v.y, w1v, a1.y);
        a1.z = fmaf(v.z, w1v, a1.z); a1.w = fmaf(v.w, w1v, a1.w);
        a2.x = fmaf(v.x, w2v, a2.x); a2.y = fmaf(v.y, w2v, a2.y);
        a2.z = fmaf(v.z, w2v, a2.z); a2.w = fmaf(v.w, w2v, a2.w);
    }

    float lg[3][4] = {{a0.x, a0.y, a0.z, a0.w}, {a1.x, a1.y, a1.z, a1.w}, {a2.x, a2.y, a2.z, a2.w}};
#pragma unroll
    for (int a = 0; a < 3; a++) {
#pragma unroll
        for (int k = 0; k < 4; k++) {
            if (lg[a][k] > OBJ_LOGIT_T) {
                int idx = atomicAdd(&g_counters[0], 1);
                if (idx < OBJ_CAP)
                    g_objCand[idx] = (n << 17) | (level << 15) | (a << 13) | (q * 4 + k);
            }
        }
    }
}

// ------------- pass 2: full 85-channel head, warp-per-row dot products -------------
__global__ void cand_kernel(const float* __restrict__ f0, const float* __restrict__ f1,
                            const float* __restrict__ f2,
                            const float* __restrict__ w0, const float* __restrict__ w1,
                            const float* __restrict__ w2,
                            const float* __restrict__ b0, const float* __restrict__ b1,
                            const float* __restrict__ b2)
{
    __shared__ __align__(16) float shf[512];
    __shared__ float lg[LCH];
    __shared__ float4 s_box;
    __shared__ float s_obj;

    int total = g_counters[0];
    if (total > OBJ_CAP) total = OBJ_CAP;

    int t = threadIdx.x;
    int warp = t >> 5, lane = t & 31;

    for (int ci = blockIdx.x; ci < total; ci += gridDim.x) {
        int pk = g_objCand[ci];
        int n = pk >> 17, level = (pk >> 15) & 3, a = (pk >> 13) & 3, hw = pk & 0x1FFF;

        const float *f, *w, *b;
        int C, HW, W, aoff;
        float stride;
        if (level == 0)      { f = f0; w = w0; b = b0; C = 128; HW = 6400; W = 80; stride = 8.f;  aoff = 0; }
        else if (level == 1) { f = f1; w = w1; b = b1; C = 256; HW = 1600; W = 40; stride = 16.f; aoff = 19200; }
        else                 { f = f2; w = w2; b = b2; C = 512; HW = 400;  W = 20; stride = 32.f; aoff = 24000; }

        for (int c = t; c < C; c += blockDim.x)
            shf[c] = f[((size_t)n * C + c) * HW + hw];
        __syncthreads();

        // warp-per-row: 4 warps cover 85 rows
        const float4* shf4 = (const float4*)shf;
        int C4 = C >> 2;
        for (int row = warp; row < LCH; row += 4) {
            const float4* wr = (const float4*)(w + (size_t)(a * LCH + row) * C);
            float acc = 0.f;
            for (int c4 = lane; c4 < C4; c4 += 32) {
                float4 wv = __ldg(wr + c4);
                float4 fv = shf4[c4];
                acc = fmaf(wv.x, fv.x, acc);
                acc = fmaf(wv.y, fv.y, acc);
                acc = fmaf(wv.z, fv.z, acc);
                acc = fmaf(wv.w, fv.w, acc);
            }
#pragma unroll
            for (int off = 16; off > 0; off >>= 1)
                acc += __shfl_xor_sync(0xFFFFFFFF, acc, off);
            if (lane == 0) lg[row] = acc + b[a * LCH + row];
        }
        __syncthreads();

        if (t == 0) {
            float px = sigf(lg[0]), py = sigf(lg[1]);
            float pw = sigf(lg[2]), ph = sigf(lg[3]);
            s_obj = sigf(lg[4]);
            int gx = hw % W, gy = hw / W;
            float2 anc = c_anchors[level][a];
            float cx = (2.f * px - 0.5f + (float)gx) * stride;
            float cy = (2.f * py - 0.5f + (float)gy) * stride;
            float bw = 4.f * pw * pw * anc.x;
            float bh = 4.f * ph * ph * anc.y;
            float x1 = cx - 0.5f * bw, y1 = cy - 0.5f * bh;
            float x2 = cx + 0.5f * bw, y2 = cy + 0.5f * bh;
            x1 = fminf(fmaxf(x1, 0.f), IMGF);
            y1 = fminf(fmaxf(y1, 0.f), IMGF);
            x2 = fminf(fmaxf(x2, 0.f), IMGF);
            y2 = fminf(fmaxf(y2, 0.f), IMGF);
            s_box = make_float4(x1, y1, x2, y2);
        }
        __syncthreads();

        if (t < NUM_CLASSES) {
            float ob = s_obj;
            if (ob > SCORE_T) {
                float s = ob * sigf(lg[5 + t]);
                if (s > SCORE_T) {
                    int pos = atomicAdd(&g_counters[1 + n], 1);
                    if (pos < DCAP) {
                        g_detScore[n][pos] = s;
                        g_detBox[n][pos]   = s_box;
                        g_detInfo[n][pos]  = (aoff + hw * 3 + a) * NUM_CLASSES + t;
                    }
                }
            }
        }
        __syncthreads();
    }
}

// ------------- pass 3: adaptive sort (top_k semantics) + greedy NMS + output -------------
__global__ void nms_kernel(const float* __restrict__ sf, float* __restrict__ out)
{
    extern __shared__ char smem[];
    unsigned long long* keys = (unsigned long long*)smem;                   // SORT_N*8
    int*    payload = (int*)   (smem + SORT_N * 8);                         // SORT_N*4
    float4* box     = (float4*)(smem + SORT_N * 12);                        // TOPK*16
    float*  scr     = (float*) (smem + SORT_N * 12 + TOPK * 16);            // TOPK*4
    int*    lab     = (int*)   (smem + SORT_N * 12 + TOPK * 20);            // TOPK*4
    int*    val     = (int*)   (smem + SORT_N * 12 + TOPK * 24);            // TOPK*4
    __shared__ int picks[DET];
    __shared__ int s_sel, s_np;

    int n = blockIdx.x;
    int tid = threadIdx.x;
    int M = g_counters[1 + n];
    if (M > DCAP) M = DCAP;
    if (tid == 0) s_np = 0;

    if (M > 0) {
        // adaptive sort width: next pow2 >= M
        int sortN = 2;
        while (sortN < M) sortN <<= 1;

        for (int i = tid; i < sortN; i += blockDim.x) {
            if (i < M) {
                unsigned u = __float_as_uint(g_detScore[n][i]);
                u = (u & 0x80000000u) ? ~u : (u | 0x80000000u);
                keys[i] = ((unsigned long long)u << 32) | (unsigned)(0x7FFFFFFF - g_detInfo[n][i]);
                payload[i] = i;
            } else {
                keys[i] = 0ULL;
                payload[i] = -1;
            }
        }
        __syncthreads();

        for (int k = 2; k <= sortN; k <<= 1) {
            for (int j = k >> 1; j > 0; j >>= 1) {
                for (int i = tid; i < sortN; i += blockDim.x) {
                    int ixj = i ^ j;
                    if (ixj > i) {
                        bool up = ((i & k) == 0);
                        unsigned long long ka = keys[i], kb = keys[ixj];
                        bool sw = up ? (ka < kb) : (ka > kb);
                        if (sw) {
                            keys[i] = kb; keys[ixj] = ka;
                            int p = payload[i]; payload[i] = payload[ixj]; payload[ixj] = p;
                        }
                    }
                }
                __syncthreads();
            }
        }

        int M2 = M < TOPK ? M : TOPK;
        for (int i = tid; i < M2; i += blockDim.x) {
            int ci = payload[i];
            box[i] = g_detBox[n][ci];
            scr[i] = g_detScore[n][ci];
            lab[i] = g_detInfo[n][ci] % NUM_CLASSES;
            val[i] = 1;
        }
        __syncthreads();

        int cursor = 0;
        for (int iter = 0; iter < DET; iter++) {
            if (tid == 0) {
                int sel = -1;
                for (int j = cursor; j < M2; j++)
                    if (val[j]) { sel = j; break; }
                s_sel = sel;
                if (sel >= 0) {
                    picks[iter] = sel;
                    val[sel] = 0;
                    s_np = iter + 1;
                    cursor = sel + 1;
                }
            }
            __syncthreads();
            int sel = s_sel;
            if (sel < 0) break;
            float4 bs = box[sel];
            int ls = lab[sel];
            float areaS = (bs.z - bs.x) * (bs.w - bs.y);
            for (int j = tid; j < M2; j += blockDim.x) {
                if (val[j] && lab[j] == ls) {
                    float4 bj = box[j];
                    float ix1 = fmaxf(bs.x, bj.x), iy1 = fmaxf(bs.y, bj.y);
                    float ix2 = fminf(bs.z, bj.z), iy2 = fminf(bs.w, bj.w);
                    float iw = fmaxf(ix2 - ix1, 0.f), ih = fmaxf(iy2 - iy1, 0.f);
                    float inter = iw * ih;
                    float aj = (bj.z - bj.x) * (bj.w - bj.y);
                    float iou = inter / (areaS + aj - inter + 1e-7f);
                    if (iou > NMS_T) val[j] = 0;
                }
            }
            __syncthreads();
        }
        __syncthreads();
    }
    __syncthreads();

    int np = s_np;
    float s = sf[n];
    for (int d = tid; d < DET; d += blockDim.x) {
        float o0 = 0, o1 = 0, o2 = 0, o3 = 0, o4 = 0, o5 = 0;
        if (d < np) {
            int p = picks[d];
            float4 bbv = box[p];
            o0 = bbv.x / s; o1 = bbv.y / s; o2 = bbv.z / s; o3 = bbv.w / s;
            o4 = scr[p];
            o5 = (float)lab[p];
        }
        float* po = out + ((size_t)n * DET + d) * 6;
        po[0] = o0; po[1] = o1; po[2] = o2; po[3] = o3; po[4] = o4; po[5] = o5;
    }
}

// ---------------- launch ----------------
extern "C" void kernel_launch(void* const* d_in, const int* in_sizes, int n_in,
                              void* d_out, int out_size)
{
    const float *f0 = nullptr, *f1 = nullptr, *f2 = nullptr;
    const float *w0 = nullptr, *w1 = nullptr, *w2 = nullptr;
    const float *bbp[3] = {nullptr, nullptr, nullptr};
    const float *sf = nullptr;
    int bcount = 0;
    for (int i = 0; i < n_in; i++) {
        const float* p = (const float*)d_in[i];
        switch (in_sizes[i]) {
            case 6553600: f0 = p; break;
            case 3276800: f1 = p; break;
            case 1638400: f2 = p; break;
            case 32640:   w0 = p; break;
            case 65280:   w1 = p; break;
            case 130560:  w2 = p; break;
            case 255:     if (bcount < 3) bbp[bcount++] = p; break;
            case 8:       sf = p; break;
            default: break;
        }
    }
    const float *b0 = bbp[0], *b1 = bbp[1], *b2 = bbp[2];
    float* out = (float*)d_out;

    void* caddr = nullptr;
    cudaGetSymbolAddress(&caddr, g_counters);
    cudaMemsetAsync(caddr, 0, 9 * sizeof(int), 0);

    obj_kernel<<<L0_BLK + L1_BLK + L2_BLK, 256>>>(f0, f1, f2, w0, w1, w2, b0, b1, b2);

    cand_kernel<<<296, 128>>>(f0, f1, f2, w0, w1, w2, b0, b1, b2);

    static int smem_set = 0;
    size_t nms_smem = SORT_N * 12 + TOPK * 28;
    if (!smem_set) {
        cudaFuncSetAttribute(nms_kernel, cudaFuncAttributeMaxDynamicSharedMemorySize, (int)nms_smem);
        smem_set = 1;
    }
    nms_kernel<<<NIMG, 256, nms_smem>>>(sf, out);
}

// round 4
// speedup vs baseline: 2.7305x; 1.0592x over previous
#include <cuda_runtime.h>
#include <math.h>

// ---------------- constants ----------------
#define NIMG 8
#define NUM_CLASSES 80
#define LCH 85
#define IMGF 640.0f
#define SCORE_T 0.1f
#define NMS_T 0.6f
#define DET 100
#define OBJ_CAP 32768
#define DCAP 4096
#define SORT_N 4096
#define TOPK 1000

// logit(0.1) = -2.197224577; wide margin (atomic-order fp32 wobble << 0.01);
// exact recheck happens in cand_kernel so superset is safe.
#define SCAN_T (-2.2072246f)

// logit buffer layout: level base + (n*3 + a)*HW + hw
#define LB0 0
#define LB1 153600            // 8*3*6400
#define LB2 192000            // LB1 + 8*3*1600
#define LTOT 201600           // LB2 + 8*3*400
// counters appended after logits: [0]=obj cand count, [1+n]=det count
__device__ __align__(16) float g_buf[LTOT + 16];
#define CNT ((int*)(g_buf + LTOT))

__constant__ float2 c_anchors[3][3] = {
    {{6.1f, 8.1f}, {20.6f, 12.6f}, {11.2f, 23.7f}},
    {{36.2f, 26.8f}, {25.9f, 57.2f}, {57.8f, 47.9f}},
    {{122.1f, 78.3f}, {73.7f, 143.8f}, {236.1f, 213.1f}},
};

__device__ int g_objCand[OBJ_CAP];                 // n<<17 | level<<15 | a<<13 | hw
__device__ float  g_detScore[NIMG][DCAP];
__device__ float4 g_detBox[NIMG][DCAP];
__device__ int    g_detInfo[NIMG][DCAP];

__device__ __forceinline__ float sigf(float x) { return 1.0f / (1.0f + expf(-x)); }

// ------------- pass 1a: channel-split partial GEMV -------------
// Block map: [0,200) L0 (50 spatial x 4 chunks), [200,304) L1 (13 x 8), [304,368) L2 (4 x 16)
#define PART_BLOCKS 368

__global__ __launch_bounds__(256) void obj_partial(
    const float* __restrict__ f0, const float* __restrict__ f1, const float* __restrict__ f2,
    const float* __restrict__ w0, const float* __restrict__ w1, const float* __restrict__ w2)
{
    __shared__ float sw[3][32];

    int blk = blockIdx.x;
    const float *f, *w;
    int C, HW, csplit, lvlbase, local;
    if (blk < 200)      { f = f0; w = w0; C = 128; HW = 6400; csplit = 4;  lvlbase = LB0; local = blk; }
    else if (blk < 304) { f = f1; w = w1; C = 256; HW = 1600; csplit = 8;  lvlbase = LB1; local = blk - 200; }
    else                { f = f2; w = w2; C = 512; HW = 400;  csplit = 16; lvlbase = LB2; local = blk - 304; }

    int sp = local / csplit;
    int chunk = local - sp * csplit;
    int c0 = chunk * 32;

    if (threadIdx.x < 96) {
        int a = threadIdx.x >> 5, cc = threadIdx.x & 31;
        sw[a][cc] = w[(a * LCH + 4) * C + c0 + cc];
    }
    __syncthreads();

    int HW4 = HW >> 2;
    int id = sp * 256 + threadIdx.x;
    if (id >= NIMG * HW4) return;
    int n = id / HW4, q = id - n * HW4;

    const float4* fb = (const float4*)f + ((size_t)n * C + c0) * HW4 + q;

    float4 A0 = make_float4(0.f, 0.f, 0.f, 0.f);
    float4 A1 = A0, A2 = A0;

#pragma unroll
    for (int cc = 0; cc < 32; cc++) {
        float4 v = __ldg(fb + (size_t)cc * HW4);
        float w0v = sw[0][cc], w1v = sw[1][cc], w2v = sw[2][cc];
        A0.x = fmaf(v.x, w0v, A0.x); A0.y = fmaf(v.y, w0v, A0.y);
        A0.z = fmaf(v.z, w0v, A0.z); A0.w = fmaf(v.w, w0v, A0.w);
        A1.x = fmaf(v.x, w1v, A1.x); A1.y = fmaf(v.y, w1v, A1.y);
        A1.z = fmaf(v.z, w1v, A1.z); A1.w = fmaf(v.w, w1v, A1.w);
        A2.x = fmaf(v.x, w2v, A2.x); A2.y = fmaf(v.y, w2v, A2.y);
        A2.z = fmaf(v.z, w2v, A2.z); A2.w = fmaf(v.w, w2v, A2.w);
    }

    int hw = q * 4;
    float* d0 = g_buf + lvlbase + (n * 3 + 0) * HW + hw;
    float* d1 = g_buf + lvlbase + (n * 3 + 1) * HW + hw;
    float* d2 = g_buf + lvlbase + (n * 3 + 2) * HW + hw;
    atomicAdd(d0 + 0, A0.x); atomicAdd(d0 + 1, A0.y); atomicAdd(d0 + 2, A0.z); atomicAdd(d0 + 3, A0.w);
    atomicAdd(d1 + 0, A1.x); atomicAdd(d1 + 1, A1.y); atomicAdd(d1 + 2, A1.z); atomicAdd(d1 + 3, A1.w);
    atomicAdd(d2 + 0, A2.x); atomicAdd(d2 + 1, A2.y); atomicAdd(d2 + 2, A2.z); atomicAdd(d2 + 3, A2.w);
}

// ------------- pass 1b: scan logits, append candidate superset -------------
#define SCAN_BLOCKS 197       // ceil(50400/256)

__global__ void obj_scan(const float* __restrict__ b0, const float* __restrict__ b1,
                         const float* __restrict__ b2)
{
    int i4 = blockIdx.x * blockDim.x + threadIdx.x;
    if (i4 >= LTOT / 4) return;
    int idx = i4 * 4;

    const float* b;
    int HW, lvl, rem;
    if (idx < LB1)      { lvl = 0; HW = 6400; b = b0; rem = idx; }
    else if (idx < LB2) { lvl = 1; HW = 1600; b = b1; rem = idx - LB1; }
    else                { lvl = 2; HW = 400;  b = b2; rem = idx - LB2; }

    int na = rem / HW;
    int hw0 = rem - na * HW;
    int n = na / 3, a = na - n * 3;
    float bias = b[a * LCH + 4];

    float4 v = *(const float4*)(g_buf + idx);
    float lg[4] = {v.x, v.y, v.z, v.w};
#pragma unroll
    for (int k = 0; k < 4; k++) {
        if (lg[k] + bias > SCAN_T) {
            int pos = atomicAdd(&CNT[0], 1);
            if (pos < OBJ_CAP)
                g_objCand[pos] = (n << 17) | (lvl << 15) | (a << 13) | (hw0 + k);
        }
    }
}

// ------------- pass 2: full 85-channel head, warp-per-row, exact recheck -------------
__global__ void cand_kernel(const float* __restrict__ f0, const float* __restrict__ f1,
                            const float* __restrict__ f2,
                            const float* __restrict__ w0, const float* __restrict__ w1,
                            const float* __restrict__ w2,
                            const float* __restrict__ b0, const float* __restrict__ b1,
                            const float* __restrict__ b2)
{
    __shared__ __align__(16) float shf[512];
    __shared__ float lg[LCH];
    __shared__ float4 s_box;
    __shared__ float s_obj;

    int total = CNT[0];
    if (total > OBJ_CAP) total = OBJ_CAP;

    int t = threadIdx.x;
    int warp = t >> 5, lane = t & 31;

    for (int ci = blockIdx.x; ci < total; ci += gridDim.x) {
        int pk = g_objCand[ci];
        int n = pk >> 17, level = (pk >> 15) & 3, a = (pk >> 13) & 3, hw = pk & 0x1FFF;

        const float *f, *w, *b;
        int C, HW, W, aoff;
        float stride;
        if (level == 0)      { f = f0; w = w0; b = b0; C = 128; HW = 6400; W = 80; stride = 8.f;  aoff = 0; }
        else if (level == 1) { f = f1; w = w1; b = b1; C = 256; HW = 1600; W = 40; stride = 16.f; aoff = 19200; }
        else                 { f = f2; w = w2; b = b2; C = 512; HW = 400;  W = 20; stride = 32.f; aoff = 24000; }

        for (int c = t; c < C; c += blockDim.x)
            shf[c] = f[((size_t)n * C + c) * HW + hw];
        __syncthreads();

        const float4* shf4 = (const float4*)shf;
        int C4 = C >> 2;
        for (int row = warp; row < LCH; row += 4) {
            const float4* wr = (const float4*)(w + (size_t)(a * LCH + row) * C);
            float acc = 0.f;
            for (int c4 = lane; c4 < C4; c4 += 32) {
                float4 wv = __ldg(wr + c4);
                float4 fv = shf4[c4];
                acc = fmaf(wv.x, fv.x, acc);
                acc = fmaf(wv.y, fv.y, acc);
                acc = fmaf(wv.z, fv.z, acc);
                acc = fmaf(wv.w, fv.w, acc);
            }
#pragma unroll
            for (int off = 16; off > 0; off >>= 1)
                acc += __shfl_xor_sync(0xFFFFFFFF, acc, off);
            if (lane == 0) lg[row] = acc + b[a * LCH + row];
        }
        __syncthreads();

        if (t == 0) {
            float px = sigf(lg[0]), py = sigf(lg[1]);
            float pw = sigf(lg[2]), ph = sigf(lg[3]);
            s_obj = sigf(lg[4]);
            int gx = hw % W, gy = hw / W;
            float2 anc = c_anchors[level][a];
            float cx = (2.f * px - 0.5f + (float)gx) * stride;
            float cy = (2.f * py - 0.5f + (float)gy) * stride;
            float bw = 4.f * pw * pw * anc.x;
            float bh = 4.f * ph * ph * anc.y;
            float x1 = cx - 0.5f * bw, y1 = cy - 0.5f * bh;
            float x2 = cx + 0.5f * bw, y2 = cy + 0.5f * bh;
            x1 = fminf(fmaxf(x1, 0.f), IMGF);
            y1 = fminf(fmaxf(y1, 0.f), IMGF);
            x2 = fminf(fmaxf(x2, 0.f), IMGF);
            y2 = fminf(fmaxf(y2, 0.f), IMGF);
            s_box = make_float4(x1, y1, x2, y2);
        }
        __syncthreads();

        if (t < NUM_CLASSES) {
            float ob = s_obj;
            if (ob > SCORE_T) {
                float s = ob * sigf(lg[5 + t]);
                if (s > SCORE_T) {
                    int pos = atomicAdd(&CNT[1 + n], 1);
                    if (pos < DCAP) {
                        g_detScore[n][pos] = s;
                        g_detBox[n][pos]   = s_box;
                        g_detInfo[n][pos]  = (aoff + hw * 3 + a) * NUM_CLASSES + t;
                    }
                }
            }
        }
        __syncthreads();
    }
}

// ------------- pass 3: adaptive sort + greedy NMS + output -------------
__global__ void nms_kernel(const float* __restrict__ sf, float* __restrict__ out)
{
    extern __shared__ char smem[];
    unsigned long long* keys = (unsigned long long*)smem;
    int*    payload = (int*)   (smem + SORT_N * 8);
    float4* box     = (float4*)(smem + SORT_N * 12);
    float*  scr     = (float*) (smem + SORT_N * 12 + TOPK * 16);
    int*    lab     = (int*)   (smem + SORT_N * 12 + TOPK * 20);
    int*    val     = (int*)   (smem + SORT_N * 12 + TOPK * 24);
    __shared__ int picks[DET];
    __shared__ int s_sel, s_np;

    int n = blockIdx.x;
    int tid = threadIdx.x;
    int M = CNT[1 + n];
    if (M > DCAP) M = DCAP;
    if (tid == 0) s_np = 0;

    if (M > 0) {
        int sortN = 2;
        while (sortN < M) sortN <<= 1;

        for (int i = tid; i < sortN; i += blockDim.x) {
            if (i < M) {
                unsigned u = __float_as_uint(g_detScore[n][i]);
                u = (u & 0x80000000u) ? ~u : (u | 0x80000000u);
                keys[i] = ((unsigned long long)u << 32) | (unsigned)(0x7FFFFFFF - g_detInfo[n][i]);
                payload[i] = i;
            } else {
                keys[i] = 0ULL;
                payload[i] = -1;
            }
        }
        __syncthreads();

        for (int k = 2; k <= sortN; k <<= 1) {
            for (int j = k >> 1; j > 0; j >>= 1) {
                for (int i = tid; i < sortN; i += blockDim.x) {
                    int ixj = i ^ j;
                    if (ixj > i) {
                        bool up = ((i & k) == 0);
                        unsigned long long ka = keys[i], kb = keys[ixj];
                        bool sw = up ? (ka < kb) : (ka > kb);
                        if (sw) {
                            keys[i] = kb; keys[ixj] = ka;
                            int p = payload[i]; payload[i] = payload[ixj]; payload[ixj] = p;
                        }
                    }
                }
                __syncthreads();
            }
        }

        int M2 = M < TOPK ? M : TOPK;
        for (int i = tid; i < M2; i += blockDim.x) {
            int ci = payload[i];
            box[i] = g_detBox[n][ci];
            scr[i] = g_detScore[n][ci];
            lab[i] = g_detInfo[n][ci] % NUM_CLASSES;
            val[i] = 1;
        }
        __syncthreads();

        int cursor = 0;
        for (int iter = 0; iter < DET; iter++) {
            if (tid == 0) {
                int sel = -1;
                for (int j = cursor; j < M2; j++)
                    if (val[j]) { sel = j; break; }
                s_sel = sel;
                if (sel >= 0) {
                    picks[iter] = sel;
                    val[sel] = 0;
                    s_np = iter + 1;
                    cursor = sel + 1;
                }
            }
            __syncthreads();
            int sel = s_sel;
            if (sel < 0) break;
            float4 bs = box[sel];
            int ls = lab[sel];
            float areaS = (bs.z - bs.x) * (bs.w - bs.y);
            for (int j = tid; j < M2; j += blockDim.x) {
                if (val[j] && lab[j] == ls) {
                    float4 bj = box[j];
                    float ix1 = fmaxf(bs.x, bj.x), iy1 = fmaxf(bs.y, bj.y);
                    float ix2 = fminf(bs.z, bj.z), iy2 = fminf(bs.w, bj.w);
                    float iw = fmaxf(ix2 - ix1, 0.f), ih = fmaxf(iy2 - iy1, 0.f);
                    float inter = iw * ih;
                    float aj = (bj.z - bj.x) * (bj.w - bj.y);
                    float iou = inter / (areaS + aj - inter + 1e-7f);
                    if (iou > NMS_T) val[j] = 0;
                }
            }
            __syncthreads();
        }
        __syncthreads();
    }
    __syncthreads();

    int np = s_np;
    float s = sf[n];
    for (int d = tid; d < DET; d += blockDim.x) {
        float o0 = 0, o1 = 0, o2 = 0, o3 = 0, o4 = 0, o5 = 0;
        if (d < np) {
            int p = picks[d];
            float4 bbv = box[p];
            o0 = bbv.x / s; o1 = bbv.y / s; o2 = bbv.z / s; o3 = bbv.w / s;
            o4 = scr[p];
            o5 = (float)lab[p];
        }
        float* po = out + ((size_t)n * DET + d) * 6;
        po[0] = o0; po[1] = o1; po[2] = o2; po[3] = o3; po[4] = o4; po[5] = o5;
    }
}

// ---------------- launch ----------------
extern "C" void kernel_launch(void* const* d_in, const int* in_sizes, int n_in,
                              void* d_out, int out_size)
{
    const float *f0 = nullptr, *f1 = nullptr, *f2 = nullptr;
    const float *w0 = nullptr, *w1 = nullptr, *w2 = nullptr;
    const float *bbp[3] = {nullptr, nullptr, nullptr};
    const float *sf = nullptr;
    int bcount = 0;
    for (int i = 0; i < n_in; i++) {
        const float* p = (const float*)d_in[i];
        switch (in_sizes[i]) {
            case 6553600: f0 = p; break;
            case 3276800: f1 = p; break;
            case 1638400: f2 = p; break;
            case 32640:   w0 = p; break;
            case 65280:   w1 = p; break;
            case 130560:  w2 = p; break;
            case 255:     if (bcount < 3) bbp[bcount++] = p; break;
            case 8:       sf = p; break;
            default: break;
        }
    }
    const float *b0 = bbp[0], *b1 = bbp[1], *b2 = bbp[2];
    float* out = (float*)d_out;

    void* baddr = nullptr;
    cudaGetSymbolAddress(&baddr, g_buf);
    cudaMemsetAsync(baddr, 0, (LTOT + 16) * sizeof(float), 0);

    obj_partial<<<PART_BLOCKS, 256>>>(f0, f1, f2, w0, w1, w2);
    obj_scan<<<SCAN_BLOCKS, 256>>>(b0, b1, b2);
    cand_kernel<<<296, 128>>>(f0, f1, f2, w0, w1, w2, b0, b1, b2);

    static int smem_set = 0;
    size_t nms_smem = SORT_N * 12 + TOPK * 28;
    if (!smem_set) {
        cudaFuncSetAttribute(nms_kernel, cudaFuncAttributeMaxDynamicSharedMemorySize, (int)nms_smem);
        smem_set = 1;
    }
    nms_kernel<<<NIMG, 256, nms_smem>>>(sf, out);
}

// round 5
// speedup vs baseline: 4.2279x; 1.5484x over previous
#include <cuda_runtime.h>
#include <math.h>

// ---------------- constants ----------------
#define NIMG 8
#define NUM_CLASSES 80
#define LCH 85
#define IMGF 640.0f
#define SCORE_T 0.1f
#define NMS_T 0.6f
#define DET 100
#define OBJ_CAP 32768
#define DCAP 4096
#define SORT_N 4096
#define TOPK 1000

// logit(0.1) = -2.197224577; margin 0.01 >> fp32 reduction-order wobble.
// Exact sigmoid recheck happens in cand_kernel, so superset is safe.
#define SCAN_T (-2.2072246f)

__constant__ float2 c_anchors[3][3] = {
    {{6.1f, 8.1f}, {20.6f, 12.6f}, {11.2f, 23.7f}},
    {{36.2f, 26.8f}, {25.9f, 57.2f}, {57.8f, 47.9f}},
    {{122.1f, 78.3f}, {73.7f, 143.8f}, {236.1f, 213.1f}},
};

// statically zero-initialized; nms_kernel re-zeros at end of every call
__device__ int g_cnt[9];                           // [0]=obj cand count, [1+n]=det count
__device__ int g_objCand[OBJ_CAP];                 // n<<17 | level<<15 | a<<13 | hw
__device__ float  g_detScore[NIMG][DCAP];
__device__ float4 g_detBox[NIMG][DCAP];
__device__ int    g_detInfo[NIMG][DCAP];

__device__ __forceinline__ float sigf(float x) { return 1.0f / (1.0f + expf(-x)); }

// ------------- pass 1: fused obj GEMV + threshold, smem reduction, direct append -------------
// CH = 8 channels (float4 rows) per thread; 256 threads = S chunks x G float4-positions.
// L0: C=128 S=16 G=16 HW=6400 -> blocks [0,800)
// L1: C=256 S=32 G=8  HW=1600 -> blocks [800,1200)
// L2: C=512 S=64 G=4  HW=400  -> blocks [1200,1400)
#define OBJ_BLOCKS 1400

__global__ __launch_bounds__(256) void obj_kernel(
    const float* __restrict__ f0, const float* __restrict__ f1, const float* __restrict__ f2,
    const float* __restrict__ w0, const float* __restrict__ w1, const float* __restrict__ w2,
    const float* __restrict__ b0, const float* __restrict__ b1, const float* __restrict__ b2)
{
    __shared__ float sw[3 * 512];
    __shared__ float sb[3];
    __shared__ float4 red[256 * 3];

    int blk = blockIdx.x;
    const float *f, *w, *b;
    int C, HW, G, level, base;
    if (blk < 800)       { f = f0; w = w0; b = b0; C = 128; HW = 6400; G = 16; level = 0; base = 0; }
    else if (blk < 1200) { f = f1; w = w1; b = b1; C = 256; HW = 1600; G = 8;  level = 1; base = 800; }
    else                 { f = f2; w = w2; b = b2; C = 512; HW = 400;  G = 4;  level = 2; base = 1200; }
    int S = 256 / G;

    int tid = threadIdx.x;
    for (int i = tid; i < 3 * C; i += 256) {
        int a = i / C, c = i - a * C;
        sw[i] = w[(a * LCH + 4) * C + c];
    }
    if (tid < 3) sb[tid] = b[tid * LCH + 4];
    __syncthreads();

    int g = tid % G;
    int s = tid / G;
    int c0 = s * 8;

    int HW4 = HW >> 2;
    int id = (blk - base) * G + g;          // exact coverage, no guard needed
    int n = id / HW4, q = id - n * HW4;

    const float4* fb = (const float4*)f + ((size_t)n * C + c0) * HW4 + q;

    float4 A0 = make_float4(0.f, 0.f, 0.f, 0.f);
    float4 A1 = A0, A2 = A0;
#pragma unroll
    for (int cc = 0; cc < 8; cc++) {
        float4 v = __ldg(fb + (size_t)cc * HW4);
        float w0v = sw[c0 + cc], w1v = sw[C + c0 + cc], w2v = sw[2 * C + c0 + cc];
        A0.x = fmaf(v.x, w0v, A0.x); A0.y = fmaf(v.y, w0v, A0.y);
        A0.z = fmaf(v.z, w0v, A0.z); A0.w = fmaf(v.w, w0v, A0.w);
        A1.x = fmaf(v.x, w1v, A1.x); A1.y = fmaf(v.y, w1v, A1.y);
        A1.z = fmaf(v.z, w1v, A1.z); A1.w = fmaf(v.w, w1v, A1.w);
        A2.x = fmaf(v.x, w2v, A2.x); A2.y = fmaf(v.y, w2v, A2.y);
        A2.z = fmaf(v.z, w2v, A2.z); A2.w = fmaf(v.w, w2v, A2.w);
    }
    red[tid * 3 + 0] = A0;
    red[tid * 3 + 1] = A1;
    red[tid * 3 + 2] = A2;
    __syncthreads();

    if (tid < 3 * G) {
        int g2 = tid % G, a2 = tid / G;
        float4 acc = red[g2 * 3 + a2];
        for (int s2 = 1; s2 < S; s2++) {
            float4 r = red[(s2 * G + g2) * 3 + a2];
            acc.x += r.x; acc.y += r.y; acc.z += r.z; acc.w += r.w;
        }
        float bias = sb[a2];
        int id2 = (blk - base) * G + g2;
        int n2 = id2 / HW4, q2 = id2 - n2 * HW4;
        float v[4] = {acc.x + bias, acc.y + bias, acc.z + bias, acc.w + bias};
#pragma unroll
        for (int k = 0; k < 4; k++) {
            if (v[k] > SCAN_T) {
                int pos = atomicAdd(&g_cnt[0], 1);
                if (pos < OBJ_CAP)
                    g_objCand[pos] = (n2 << 17) | (level << 15) | (a2 << 13) | (q2 * 4 + k);
            }
        }
    }
}

// ------------- pass 2: full 85-channel head, 8 warps per block, exact recheck -------------
__global__ __launch_bounds__(256) void cand_kernel(
    const float* __restrict__ f0, const float* __restrict__ f1, const float* __restrict__ f2,
    const float* __restrict__ w0, const float* __restrict__ w1, const float* __restrict__ w2,
    const float* __restrict__ b0, const float* __restrict__ b1, const float* __restrict__ b2)
{
    __shared__ __align__(16) float shf[512];
    __shared__ float lg[LCH];
    __shared__ float4 s_box;
    __shared__ float s_obj;

    int total = g_cnt[0];
    if (total > OBJ_CAP) total = OBJ_CAP;

    int t = threadIdx.x;
    int warp = t >> 5, lane = t & 31;

    for (int ci = blockIdx.x; ci < total; ci += gridDim.x) {
        int pk = g_objCand[ci];
        int n = pk >> 17, level = (pk >> 15) & 3, a = (pk >> 13) & 3, hw = pk & 0x1FFF;

        const float *f, *w, *b;
        int C, HW, W, aoff;
        float stride;
        if (level == 0)      { f = f0; w = w0; b = b0; C = 128; HW = 6400; W = 80; stride = 8.f;  aoff = 0; }
        else if (level == 1) { f = f1; w = w1; b = b1; C = 256; HW = 1600; W = 40; stride = 16.f; aoff = 19200; }
        else                 { f = f2; w = w2; b = b2; C = 512; HW = 400;  W = 20; stride = 32.f; aoff = 24000; }

        for (int c = t; c < C; c += 256)
            shf[c] = f[((size_t)n * C + c) * HW + hw];
        __syncthreads();

        const float4* shf4 = (const float4*)shf;
        int C4 = C >> 2;
        for (int row = warp; row < LCH; row += 8) {
            const float4* wr = (const float4*)(w + (size_t)(a * LCH + row) * C);
            float acc = 0.f;
            for (int c4 = lane; c4 < C4; c4 += 32) {
                float4 wv = __ldg(wr + c4);
                float4 fv = shf4[c4];
                acc = fmaf(wv.x, fv.x, acc);
                acc = fmaf(wv.y, fv.y, acc);
                acc = fmaf(wv.z, fv.z, acc);
                acc = fmaf(wv.w, fv.w, acc);
            }
#pragma unroll
            for (int off = 16; off > 0; off >>= 1)
                acc += __shfl_xor_sync(0xFFFFFFFF, acc, off);
            if (lane == 0) lg[row] = acc + b[a * LCH + row];
        }
        __syncthreads();

        if (t == 0) {
            float px = sigf(lg[0]), py = sigf(lg[1]);
            float pw = sigf(lg[2]), ph = sigf(lg[3]);
            s_obj = sigf(lg[4]);
            int gx = hw % W, gy = hw / W;
            float2 anc = c_anchors[level][a];
            float cx = (2.f * px - 0.5f + (float)gx) * stride;
            float cy = (2.f * py - 0.5f + (float)gy) * stride;
            float bw = 4.f * pw * pw * anc.x;
            float bh = 4.f * ph * ph * anc.y;
            float x1 = cx - 0.5f * bw, y1 = cy - 0.5f * bh;
            float x2 = cx + 0.5f * bw, y2 = cy + 0.5f * bh;
            x1 = fminf(fmaxf(x1, 0.f), IMGF);
            y1 = fminf(fmaxf(y1, 0.f), IMGF);
            x2 = fminf(fmaxf(x2, 0.f), IMGF);
            y2 = fminf(fmaxf(y2, 0.f), IMGF);
            s_box = make_float4(x1, y1, x2, y2);
        }
        __syncthreads();

        if (t < NUM_CLASSES) {
            float ob = s_obj;
            if (ob > SCORE_T) {
                float s = ob * sigf(lg[5 + t]);
                if (s > SCORE_T) {
                    int pos = atomicAdd(&g_cnt[1 + n], 1);
                    if (pos < DCAP) {
                        g_detScore[n][pos] = s;
                        g_detBox[n][pos]   = s_box;
                        g_detInfo[n][pos]  = (aoff + hw * 3 + a) * NUM_CLASSES + t;
                    }
                }
            }
        }
        __syncthreads();
    }
}

// ------------- pass 3: adaptive sort + greedy NMS + output + counter reset -------------
__global__ void nms_kernel(const float* __restrict__ sf, float* __restrict__ out)
{
    extern __shared__ char smem[];
    unsigned long long* keys = (unsigned long long*)smem;
    int*    payload = (int*)   (smem + SORT_N * 8);
    float4* box     = (float4*)(smem + SORT_N * 12);
    float*  scr     = (float*) (smem + SORT_N * 12 + TOPK * 16);
    int*    lab     = (int*)   (smem + SORT_N * 12 + TOPK * 20);
    int*    val     = (int*)   (smem + SORT_N * 12 + TOPK * 24);
    __shared__ int picks[DET];
    __shared__ int s_sel, s_np;

    int n = blockIdx.x;
    int tid = threadIdx.x;
    int M = g_cnt[1 + n];
    if (M > DCAP) M = DCAP;
    if (tid == 0) s_np = 0;

    if (M > 0) {
        int sortN = 2;
        while (sortN < M) sortN <<= 1;

        for (int i = tid; i < sortN; i += blockDim.x) {
            if (i < M) {
                unsigned u = __float_as_uint(g_detScore[n][i]);
                u = (u & 0x80000000u) ? ~u : (u | 0x80000000u);
                keys[i] = ((unsigned long long)u << 32) | (unsigned)(0x7FFFFFFF - g_detInfo[n][i]);
                payload[i] = i;
            } else {
                keys[i] = 0ULL;
                payload[i] = -1;
            }
        }
        __syncthreads();

        for (int k = 2; k <= sortN; k <<= 1) {
            for (int j = k >> 1; j > 0; j >>= 1) {
                for (int i = tid; i < sortN; i += blockDim.x) {
                    int ixj = i ^ j;
                    if (ixj > i) {
                        bool up = ((i & k) == 0);
                        unsigned long long ka = keys[i], kb = keys[ixj];
                        bool sw = up ? (ka < kb) : (ka > kb);
                        if (sw) {
                            keys[i] = kb; keys[ixj] = ka;
                            int p = payload[i]; payload[i] = payload[ixj]; payload[ixj] = p;
                        }
                    }
                }
                __syncthreads();
            }
        }

        int M2 = M < TOPK ? M : TOPK;
        for (int i = tid; i < M2; i += blockDim.x) {
            int ci = payload[i];
            box[i] = g_detBox[n][ci];
            scr[i] = g_detScore[n][ci];
            lab[i] = g_detInfo[n][ci] % NUM_CLASSES;
            val[i] = 1;
        }
        __syncthreads();

        int cursor = 0;
        for (int iter = 0; iter < DET; iter++) {
            if (tid == 0) {
                int sel = -1;
                for (int j = cursor; j < M2; j++)
                    if (val[j]) { sel = j; break; }
                s_sel = sel;
                if (sel >= 0) {
                    picks[iter] = sel;
                    val[sel] = 0;
                    s_np = iter + 1;
                    cursor = sel + 1;
                }
            }
            __syncthreads();
            int sel = s_sel;
            if (sel < 0) break;
            float4 bs = box[sel];
            int ls = lab[sel];
            float areaS = (bs.z - bs.x) * (bs.w - bs.y);
            for (int j = tid; j < M2; j += blockDim.x) {
                if (val[j] && lab[j] == ls) {
                    float4 bj = box[j];
                    float ix1 = fmaxf(bs.x, bj.x), iy1 = fmaxf(bs.y, bj.y);
                    float ix2 = fminf(bs.z, bj.z), iy2 = fminf(bs.w, bj.w);
                    float iw = fmaxf(ix2 - ix1, 0.f), ih = fmaxf(iy2 - iy1, 0.f);
                    float inter = iw * ih;
                    float aj = (bj.z - bj.x) * (bj.w - bj.y);
                    float iou = inter / (areaS + aj - inter + 1e-7f);
                    if (iou > NMS_T) val[j] = 0;
                }
            }
            __syncthreads();
        }
        __syncthreads();
    }
    __syncthreads();

    int np = s_np;
    float s = sf[n];
    for (int d = tid; d < DET; d += blockDim.x) {
        float o0 = 0, o1 = 0, o2 = 0, o3 = 0, o4 = 0, o5 = 0;
        if (d < np) {
            int p = picks[d];
            float4 bbv = box[p];
            o0 = bbv.x / s; o1 = bbv.y / s; o2 = bbv.z / s; o3 = bbv.w / s;
            o4 = scr[p];
            o5 = (float)lab[p];
        }
        float* po = out + ((size_t)n * DET + d) * 6;
        po[0] = o0; po[1] = o1; po[2] = o2; po[3] = o3; po[4] = o4; po[5] = o5;
    }

    // reset counters for the next (graph-replayed) call — inputs to this kernel
    // are already consumed; each block owns its own counter.
    __syncthreads();
    if (tid == 0) {
        g_cnt[1 + n] = 0;
        if (n == 0) g_cnt[0] = 0;
    }
}

// ---------------- launch ----------------
extern "C" void kernel_launch(void* const* d_in, const int* in_sizes, int n_in,
                              void* d_out, int out_size)
{
    const float *f0 = nullptr, *f1 = nullptr, *f2 = nullptr;
    const float *w0 = nullptr, *w1 = nullptr, *w2 = nullptr;
    const float *bbp[3] = {nullptr, nullptr, nullptr};
    const float *sf = nullptr;
    int bcount = 0;
    for (int i = 0; i < n_in; i++) {
        const float* p = (const float*)d_in[i];
        switch (in_sizes[i]) {
            case 6553600: f0 = p; break;
            case 3276800: f1 = p; break;
            case 1638400: f2 = p; break;
            case 32640:   w0 = p; break;
            case 65280:   w1 = p; break;
            case 130560:  w2 = p; break;
            case 255:     if (bcount < 3) bbp[bcount++] = p; break;
            case 8:       sf = p; break;
            default: break;
        }
    }
    const float *b0 = bbp[0], *b1 = bbp[1], *b2 = bbp[2];
    float* out = (float*)d_out;

    obj_kernel<<<OBJ_BLOCKS, 256>>>(f0, f1, f2, w0, w1, w2, b0, b1, b2);
    cand_kernel<<<296, 256>>>(f0, f1, f2, w0, w1, w2, b0, b1, b2);

    static int smem_set = 0;
    size_t nms_smem = SORT_N * 12 + TOPK * 28;
    if (!smem_set) {
        cudaFuncSetAttribute(nms_kernel, cudaFuncAttributeMaxDynamicSharedMemorySize, (int)nms_smem);
        smem_set = 1;
    }
    nms_kernel<<<NIMG, 256, nms_smem>>>(sf, out);
}

// round 6
// speedup vs baseline: 5.4101x; 1.2796x over previous
#include <cuda_runtime.h>
#include <math.h>

// ---------------- constants ----------------
#define NIMG 8
#define NUM_CLASSES 80
#define LCH 85
#define IMGF 640.0f
#define SCORE_T 0.1f
#define NMS_T 0.6f
#define DET 100
#define OBJ_CAP 32768
#define DCAP 4096
#define SORT_N 4096
#define TOPK 1000

// logit(0.1) = -2.197224577; margin 0.01 >> fp32 reduction-order wobble.
// Exact sigmoid recheck happens in cand_kernel, so superset is safe.
#define SCAN_T (-2.2072246f)

__constant__ float2 c_anchors[3][3] = {
    {{6.1f, 8.1f}, {20.6f, 12.6f}, {11.2f, 23.7f}},
    {{36.2f, 26.8f}, {25.9f, 57.2f}, {57.8f, 47.9f}},
    {{122.1f, 78.3f}, {73.7f, 143.8f}, {236.1f, 213.1f}},
};

// statically zero-initialized; nms_kernel re-zeros at end of every call
__device__ int g_cnt[9];                           // [0]=obj cand count, [1+n]=det count
__device__ int g_objCand[OBJ_CAP];                 // n<<17 | level<<15 | a<<13 | hw
__device__ float  g_detScore[NIMG][DCAP];
__device__ float4 g_detBox[NIMG][DCAP];
__device__ int    g_detInfo[NIMG][DCAP];

__device__ __forceinline__ float sigf(float x) { return 1.0f / (1.0f + expf(-x)); }

// ------------- pass 1: obj GEMV, lane=position / warp=channel-chunk -------------
// 256 threads = 8 warps. Each block covers 32 float4-positions (128 spatial).
// L0: C=128 HW=6400 -> 400 blocks   L1: C=256 HW=1600 -> 100 blocks
// L2: C=512 HW=400  -> 25 blocks    total 525
#define OBJ_BLOCKS 525

template<int C, int HW, int LEVEL>
__device__ __forceinline__ void obj_level(
    const float* __restrict__ f, const float* __restrict__ wgt, const float* __restrict__ b,
    int blkLocal, float* sw, float4* red, float* sb)
{
    constexpr int CH  = C / 8;       // channels per warp
    constexpr int HW4 = HW / 4;

    int tid  = threadIdx.x;
    int warp = tid >> 5, lane = tid & 31;

    for (int i = tid; i < 3 * C; i += 256) {
        int a = i / C, c = i - a * C;
        sw[i] = wgt[(a * LCH + 4) * C + c];
    }
    if (tid < 3) sb[tid] = b[tid * LCH + 4];
    __syncthreads();

    int id = blkLocal * 32 + lane;               // flattened n*HW4+q, exact coverage
    int n = id / HW4, q = id - n * HW4;
    int c0 = warp * CH;

    const float4* fb = (const float4*)f + ((size_t)n * C + c0) * HW4 + q;

    float4 A0 = make_float4(0.f, 0.f, 0.f, 0.f);
    float4 A1 = A0, A2 = A0;
#pragma unroll (CH > 32 ? 32 : CH)
    for (int cc = 0; cc < CH; cc++) {
        float4 v = __ldg(fb + (size_t)cc * HW4);
        float w0v = sw[c0 + cc], w1v = sw[C + c0 + cc], w2v = sw[2 * C + c0 + cc];
        A0.x = fmaf(v.x, w0v, A0.x); A0.y = fmaf(v.y, w0v, A0.y);
        A0.z = fmaf(v.z, w0v, A0.z); A0.w = fmaf(v.w, w0v, A0.w);
        A1.x = fmaf(v.x, w1v, A1.x); A1.y = fmaf(v.y, w1v, A1.y);
        A1.z = fmaf(v.z, w1v, A1.z); A1.w = fmaf(v.w, w1v, A1.w);
        A2.x = fmaf(v.x, w2v, A2.x); A2.y = fmaf(v.y, w2v, A2.y);
        A2.z = fmaf(v.z, w2v, A2.z); A2.w = fmaf(v.w, w2v, A2.w);
    }
    // red layout [a][warp][lane]: writes and reads both conflict-free
    red[(0 * 8 + warp) * 32 + lane] = A0;
    red[(1 * 8 + warp) * 32 + lane] = A1;
    red[(2 * 8 + warp) * 32 + lane] = A2;
    __syncthreads();

    if (tid < 96) {
        int a2 = tid >> 5, l2 = tid & 31;
        float4 acc = red[(a2 * 8 + 0) * 32 + l2];
#pragma unroll
        for (int w2 = 1; w2 < 8; w2++) {
            float4 r = red[(a2 * 8 + w2) * 32 + l2];
            acc.x += r.x; acc.y += r.y; acc.z += r.z; acc.w += r.w;
        }
        float bias = sb[a2];
        int id2 = blkLocal * 32 + l2;
        int n2 = id2 / HW4, q2 = id2 - n2 * HW4;
        float v[4] = {acc.x + bias, acc.y + bias, acc.z + bias, acc.w + bias};
#pragma unroll
        for (int k = 0; k < 4; k++) {
            if (v[k] > SCAN_T) {
                int pos = atomicAdd(&g_cnt[0], 1);
                if (pos < OBJ_CAP)
                    g_objCand[pos] = (n2 << 17) | (LEVEL << 15) | (a2 << 13) | (q2 * 4 + k);
            }
        }
    }
}

__global__ __launch_bounds__(256) void obj_kernel(
    const float* __restrict__ f0, const float* __restrict__ f1, const float* __restrict__ f2,
    const float* __restrict__ w0, const float* __restrict__ w1, const float* __restrict__ w2,
    const float* __restrict__ b0, const float* __restrict__ b1, const float* __restrict__ b2)
{
    __shared__ float sw[3 * 512];
    __shared__ float4 red[3 * 8 * 32];
    __shared__ float sb[3];

    int blk = blockIdx.x;
    if (blk < 400)      obj_level<128, 6400, 0>(f0, w0, b0, blk,       sw, red, sb);
    else if (blk < 500) obj_level<256, 1600, 1>(f1, w1, b1, blk - 400, sw, red, sb);
    else                obj_level<512, 400,  2>(f2, w2, b2, blk - 500, sw, red, sb);
}

// ------------- pass 2: full 85-channel head, 8 warps per block, exact recheck -------------
__global__ __launch_bounds__(256) void cand_kernel(
    const float* __restrict__ f0, const float* __restrict__ f1, const float* __restrict__ f2,
    const float* __restrict__ w0, const float* __restrict__ w1, const float* __restrict__ w2,
    const float* __restrict__ b0, const float* __restrict__ b1, const float* __restrict__ b2)
{
    __shared__ __align__(16) float shf[512];
    __shared__ float lg[LCH];
    __shared__ float4 s_box;
    __shared__ float s_obj;

    int total = g_cnt[0];
    if (total > OBJ_CAP) total = OBJ_CAP;

    int t = threadIdx.x;
    int warp = t >> 5, lane = t & 31;

    for (int ci = blockIdx.x; ci < total; ci += gridDim.x) {
        int pk = g_objCand[ci];
        int n = pk >> 17, level = (pk >> 15) & 3, a = (pk >> 13) & 3, hw = pk & 0x1FFF;

        const float *f, *w, *b;
        int C, HW, W, aoff;
        float stride;
        if (level == 0)      { f = f0; w = w0; b = b0; C = 128; HW = 6400; W = 80; stride = 8.f;  aoff = 0; }
        else if (level == 1) { f = f1; w = w1; b = b1; C = 256; HW = 1600; W = 40; stride = 16.f; aoff = 19200; }
        else                 { f = f2; w = w2; b = b2; C = 512; HW = 400;  W = 20; stride = 32.f; aoff = 24000; }

        for (int c = t; c < C; c += 256)
            shf[c] = f[((size_t)n * C + c) * HW + hw];
        __syncthreads();

        const float4* shf4 = (const float4*)shf;
        int C4 = C >> 2;
        for (int row = warp; row < LCH; row += 8) {
            const float4* wr = (const float4*)(w + (size_t)(a * LCH + row) * C);
            float acc = 0.f;
            for (int c4 = lane; c4 < C4; c4 += 32) {
                float4 wv = __ldg(wr + c4);
                float4 fv = shf4[c4];
                acc = fmaf(wv.x, fv.x, acc);
                acc = fmaf(wv.y, fv.y, acc);
                acc = fmaf(wv.z, fv.z, acc);
                acc = fmaf(wv.w, fv.w, acc);
            }
#pragma unroll
            for (int off = 16; off > 0; off >>= 1)
                acc += __shfl_xor_sync(0xFFFFFFFF, acc, off);
            if (lane == 0) lg[row] = acc + b[a * LCH + row];
        }
        __syncthreads();

        if (t == 0) {
            float px = sigf(lg[0]), py = sigf(lg[1]);
            float pw = sigf(lg[2]), ph = sigf(lg[3]);
            s_obj = sigf(lg[4]);
            int gx = hw % W, gy = hw / W;
            float2 anc = c_anchors[level][a];
            float cx = (2.f * px - 0.5f + (float)gx) * stride;
            float cy = (2.f * py - 0.5f + (float)gy) * stride;
            float bw = 4.f * pw * pw * anc.x;
            float bh = 4.f * ph * ph * anc.y;
            float x1 = cx - 0.5f * bw, y1 = cy - 0.5f * bh;
            float x2 = cx + 0.5f * bw, y2 = cy + 0.5f * bh;
            x1 = fminf(fmaxf(x1, 0.f), IMGF);
            y1 = fminf(fmaxf(y1, 0.f), IMGF);
            x2 = fminf(fmaxf(x2, 0.f), IMGF);
            y2 = fminf(fmaxf(y2, 0.f), IMGF);
            s_box = make_float4(x1, y1, x2, y2);
        }
        __syncthreads();

        if (t < NUM_CLASSES) {
            float ob = s_obj;
            if (ob > SCORE_T) {
                float s = ob * sigf(lg[5 + t]);
                if (s > SCORE_T) {
                    int pos = atomicAdd(&g_cnt[1 + n], 1);
                    if (pos < DCAP) {
                        g_detScore[n][pos] = s;
                        g_detBox[n][pos]   = s_box;
                        g_detInfo[n][pos]  = (aoff + hw * 3 + a) * NUM_CLASSES + t;
                    }
                }
            }
        }
        __syncthreads();
    }
}

// ------------- pass 3: adaptive sort + greedy NMS + output + counter reset -------------
__global__ void nms_kernel(const float* __restrict__ sf, float* __restrict__ out)
{
    extern __shared__ char smem[];
    unsigned long long* keys = (unsigned long long*)smem;
    int*    payload = (int*)   (smem + SORT_N * 8);
    float4* box     = (float4*)(smem + SORT_N * 12);
    float*  scr     = (float*) (smem + SORT_N * 12 + TOPK * 16);
    int*    lab     = (int*)   (smem + SORT_N * 12 + TOPK * 20);
    int*    val     = (int*)   (smem + SORT_N * 12 + TOPK * 24);
    __shared__ int picks[DET];
    __shared__ int s_sel, s_np;

    int n = blockIdx.x;
    int tid = threadIdx.x;
    int M = g_cnt[1 + n];
    if (M > DCAP) M = DCAP;
    if (tid == 0) s_np = 0;

    if (M > 0) {
        int sortN = 2;
        while (sortN < M) sortN <<= 1;

        for (int i = tid; i < sortN; i += blockDim.x) {
            if (i < M) {
                unsigned u = __float_as_uint(g_detScore[n][i]);
                u = (u & 0x80000000u) ? ~u : (u | 0x80000000u);
                keys[i] = ((unsigned long long)u << 32) | (unsigned)(0x7FFFFFFF - g_detInfo[n][i]);
                payload[i] = i;
            } else {
                keys[i] = 0ULL;
                payload[i] = -1;
            }
        }
        __syncthreads();

        for (int k = 2; k <= sortN; k <<= 1) {
            for (int j = k >> 1; j > 0; j >>= 1) {
                for (int i = tid; i < sortN; i += blockDim.x) {
                    int ixj = i ^ j;
                    if (ixj > i) {
                        bool up = ((i & k) == 0);
                        unsigned long long ka = keys[i], kb = keys[ixj];
                        bool sw = up ? (ka < kb) : (ka > kb);
                        if (sw) {
                            keys[i] = kb; keys[ixj] = ka;
                            int p = payload[i]; payload[i] = payload[ixj]; payload[ixj] = p;
                        }
                    }
                }
                __syncthreads();
            }
        }

        int M2 = M < TOPK ? M : TOPK;
        for (int i = tid; i < M2; i += blockDim.x) {
            int ci = payload[i];
            box[i] = g_detBox[n][ci];
            scr[i] = g_detScore[n][ci];
            lab[i] = g_detInfo[n][ci] % NUM_CLASSES;
            val[i] = 1;
        }
        __syncthreads();

        int cursor = 0;
        for (int iter = 0; iter < DET; iter++) {
            if (tid == 0) {
                int sel = -1;
                for (int j = cursor; j < M2; j++)
                    if (val[j]) { sel = j; break; }
                s_sel = sel;
                if (sel >= 0) {
                    picks[iter] = sel;
                    val[sel] = 0;
                    s_np = iter + 1;
                    cursor = sel + 1;
                }
            }
            __syncthreads();
            int sel = s_sel;
            if (sel < 0) break;
            float4 bs = box[sel];
            int ls = lab[sel];
            float areaS = (bs.z - bs.x) * (bs.w - bs.y);
            for (int j = tid; j < M2; j += blockDim.x) {
                if (val[j] && lab[j] == ls) {
                    float4 bj = box[j];
                    float ix1 = fmaxf(bs.x, bj.x), iy1 = fmaxf(bs.y, bj.y);
                    float ix2 = fminf(bs.z, bj.z), iy2 = fminf(bs.w, bj.w);
                    float iw = fmaxf(ix2 - ix1, 0.f), ih = fmaxf(iy2 - iy1, 0.f);
                    float inter = iw * ih;
                    float aj = (bj.z - bj.x) * (bj.w - bj.y);
                    float iou = inter / (areaS + aj - inter + 1e-7f);
                    if (iou > NMS_T) val[j] = 0;
                }
            }
            __syncthreads();
        }
        __syncthreads();
    }
    __syncthreads();

    int np = s_np;
    float s = sf[n];
    for (int d = tid; d < DET; d += blockDim.x) {
        float o0 = 0, o1 = 0, o2 = 0, o3 = 0, o4 = 0, o5 = 0;
        if (d < np) {
            int p = picks[d];
            float4 bbv = box[p];
            o0 = bbv.x / s; o1 = bbv.y / s; o2 = bbv.z / s; o3 = bbv.w / s;
            o4 = scr[p];
            o5 = (float)lab[p];
        }
        float* po = out + ((size_t)n * DET + d) * 6;
        po[0] = o0; po[1] = o1; po[2] = o2; po[3] = o3; po[4] = o4; po[5] = o5;
    }

    // reset counters for the next (graph-replayed) call
    __syncthreads();
    if (tid == 0) {
        g_cnt[1 + n] = 0;
        if (n == 0) g_cnt[0] = 0;
    }
}

// ---------------- launch ----------------
extern "C" void kernel_launch(void* const* d_in, const int* in_sizes, int n_in,
                              void* d_out, int out_size)
{
    const float *f0 = nullptr, *f1 = nullptr, *f2 = nullptr;
    const float *w0 = nullptr, *w1 = nullptr, *w2 = nullptr;
    const float *bbp[3] = {nullptr, nullptr, nullptr};
    const float *sf = nullptr;
    int bcount = 0;
    for (int i = 0; i < n_in; i++) {
        const float* p = (const float*)d_in[i];
        switch (in_sizes[i]) {
            case 6553600: f0 = p; break;
            case 3276800: f1 = p; break;
            case 1638400: f2 = p; break;
            case 32640:   w0 = p; break;
            case 65280:   w1 = p; break;
            case 130560:  w2 = p; break;
            case 255:     if (bcount < 3) bbp[bcount++] = p; break;
            case 8:       sf = p; break;
            default: break;
        }
    }
    const float *b0 = bbp[0], *b1 = bbp[1], *b2 = bbp[2];
    float* out = (float*)d_out;

    obj_kernel<<<OBJ_BLOCKS, 256>>>(f0, f1, f2, w0, w1, w2, b0, b1, b2);
    cand_kernel<<<320, 256>>>(f0, f1, f2, w0, w1, w2, b0, b1, b2);

    static int smem_set = 0;
    size_t nms_smem = SORT_N * 12 + TOPK * 28;
    if (!smem_set) {
        cudaFuncSetAttribute(nms_kernel, cudaFuncAttributeMaxDynamicSharedMemorySize, (int)nms_smem);
        smem_set = 1;
    }
    nms_kernel<<<NIMG, 256, nms_smem>>>(sf, out);
}

// round 7
// speedup vs baseline: 5.8253x; 1.0767x over previous
#include <cuda_runtime.h>
#include <math.h>

// ---------------- constants ----------------
#define NIMG 8
#define NUM_CLASSES 80
#define LCH 85
#define IMGF 640.0f
#define SCORE_T 0.1f
#define NMS_T 0.6f
#define DET 100
#define OBJ_CAP 32768
#define DCAP 4096
#define SORT_N 4096
#define TOPK 1000

// logit(0.1) = -2.197224577; margin 0.01 >> fp32 reduction-order wobble.
// Exact sigmoid recheck happens in cand_kernel, so superset is safe.
#define SCAN_T (-2.2072246f)

__constant__ float2 c_anchors[3][3] = {
    {{6.1f, 8.1f}, {20.6f, 12.6f}, {11.2f, 23.7f}},
    {{36.2f, 26.8f}, {25.9f, 57.2f}, {57.8f, 47.9f}},
    {{122.1f, 78.3f}, {73.7f, 143.8f}, {236.1f, 213.1f}},
};

// statically zero-initialized; nms_kernel re-zeros at end of every call
__device__ int g_cnt[9];                           // [0]=obj cand count, [1+n]=det count
__device__ int g_objCand[OBJ_CAP];                 // n<<17 | level<<15 | a<<13 | hw
__device__ float  g_detScore[NIMG][DCAP];
__device__ float4 g_detBox[NIMG][DCAP];
__device__ int    g_detInfo[NIMG][DCAP];

__device__ __forceinline__ float sigf(float x) { return 1.0f / (1.0f + expf(-x)); }

// ------------- pass 1: obj GEMV, uniform 64KB tiles -------------
// Block tile = P float4-positions x C channels; CH = 16 channels/thread always.
// L0: C=128 P=32 -> 400 blocks   L1: C=256 P=16 -> 200 blocks
// L2: C=512 P=8  -> 100 blocks   total 700 uniform blocks
#define OBJ_BLOCKS 700

template<int C, int HW, int LEVEL, int P>
__device__ __forceinline__ void obj_level(
    const float* __restrict__ f, const float* __restrict__ wgt, const float* __restrict__ b,
    int blkLocal, float* sw, float4* red, float* sb)
{
    constexpr int HW4  = HW / 4;
    constexpr int STOT = 256 / P;        // total channel splits
    constexpr int CH   = C / STOT;       // = 16 channels per thread

    int tid  = threadIdx.x;
    int warp = tid >> 5, lane = tid & 31;

    for (int i = tid; i < 3 * C; i += 256) {
        int a = i / C, c = i - a * C;
        sw[i] = wgt[(a * LCH + 4) * C + c];
    }
    if (tid < 3) sb[tid] = b[tid * LCH + 4];
    __syncthreads();

    int pos   = lane % P;
    int sub   = lane / P;
    int split = warp * (32 / P) + sub;
    int c0    = split * CH;

    int id = blkLocal * P + pos;                 // flattened n*HW4+q, exact coverage
    int n = id / HW4, q = id - n * HW4;

    const float4* fb = (const float4*)f + ((size_t)n * C + c0) * HW4 + q;

    float4 A0 = make_float4(0.f, 0.f, 0.f, 0.f);
    float4 A1 = A0, A2 = A0;
#pragma unroll
    for (int cc = 0; cc < CH; cc++) {
        float4 v = __ldg(fb + (size_t)cc * HW4);
        float w0v = sw[c0 + cc], w1v = sw[C + c0 + cc], w2v = sw[2 * C + c0 + cc];
        A0.x = fmaf(v.x, w0v, A0.x); A0.y = fmaf(v.y, w0v, A0.y);
        A0.z = fmaf(v.z, w0v, A0.z); A0.w = fmaf(v.w, w0v, A0.w);
        A1.x = fmaf(v.x, w1v, A1.x); A1.y = fmaf(v.y, w1v, A1.y);
        A1.z = fmaf(v.z, w1v, A1.z); A1.w = fmaf(v.w, w1v, A1.w);
        A2.x = fmaf(v.x, w2v, A2.x); A2.y = fmaf(v.y, w2v, A2.y);
        A2.z = fmaf(v.z, w2v, A2.z); A2.w = fmaf(v.w, w2v, A2.w);
    }
    // red[a][split][pos]; split*P+pos == warp*32+lane -> conflict-free
    red[0 * 256 + split * P + pos] = A0;
    red[1 * 256 + split * P + pos] = A1;
    red[2 * 256 + split * P + pos] = A2;
    __syncthreads();

    if (tid < 3 * P) {
        int a2 = tid / P, p2 = tid % P;
        float4 acc = red[a2 * 256 + p2];
#pragma unroll
        for (int s2 = 1; s2 < STOT; s2++) {
            float4 r = red[a2 * 256 + s2 * P + p2];
            acc.x += r.x; acc.y += r.y; acc.z += r.z; acc.w += r.w;
        }
        float bias = sb[a2];
        int id2 = blkLocal * P + p2;
        int n2 = id2 / HW4, q2 = id2 - n2 * HW4;
        float v[4] = {acc.x + bias, acc.y + bias, acc.z + bias, acc.w + bias};
#pragma unroll
        for (int k = 0; k < 4; k++) {
            if (v[k] > SCAN_T) {
                int p = atomicAdd(&g_cnt[0], 1);
                if (p < OBJ_CAP)
                    g_objCand[p] = (n2 << 17) | (LEVEL << 15) | (a2 << 13) | (q2 * 4 + k);
            }
        }
    }
}

__global__ __launch_bounds__(256, 5) void obj_kernel(
    const float* __restrict__ f0, const float* __restrict__ f1, const float* __restrict__ f2,
    const float* __restrict__ w0, const float* __restrict__ w1, const float* __restrict__ w2,
    const float* __restrict__ b0, const float* __restrict__ b1, const float* __restrict__ b2)
{
    __shared__ float sw[3 * 512];
    __shared__ float4 red[3 * 256];
    __shared__ float sb[3];

    int blk = blockIdx.x;
    if (blk < 400)      obj_level<128, 6400, 0, 32>(f0, w0, b0, blk,       sw, red, sb);
    else if (blk < 600) obj_level<256, 1600, 1, 16>(f1, w1, b1, blk - 400, sw, red, sb);
    else                obj_level<512, 400,  2, 8 >(f2, w2, b2, blk - 600, sw, red, sb);
}

// ------------- pass 2: full 85-channel head, 8 warps per block, exact recheck -------------
__global__ __launch_bounds__(256) void cand_kernel(
    const float* __restrict__ f0, const float* __restrict__ f1, const float* __restrict__ f2,
    const float* __restrict__ w0, const float* __restrict__ w1, const float* __restrict__ w2,
    const float* __restrict__ b0, const float* __restrict__ b1, const float* __restrict__ b2)
{
    __shared__ __align__(16) float shf[512];
    __shared__ float lg[LCH];
    __shared__ float4 s_box;
    __shared__ float s_obj;

    int total = g_cnt[0];
    if (total > OBJ_CAP) total = OBJ_CAP;

    int t = threadIdx.x;
    int warp = t >> 5, lane = t & 31;

    for (int ci = blockIdx.x; ci < total; ci += gridDim.x) {
        int pk = g_objCand[ci];
        int n = pk >> 17, level = (pk >> 15) & 3, a = (pk >> 13) & 3, hw = pk & 0x1FFF;

        const float *f, *w, *b;
        int C, HW, W, aoff;
        float stride;
        if (level == 0)      { f = f0; w = w0; b = b0; C = 128; HW = 6400; W = 80; stride = 8.f;  aoff = 0; }
        else if (level == 1) { f = f1; w = w1; b = b1; C = 256; HW = 1600; W = 40; stride = 16.f; aoff = 19200; }
        else                 { f = f2; w = w2; b = b2; C = 512; HW = 400;  W = 20; stride = 32.f; aoff = 24000; }

        for (int c = t; c < C; c += 256)
            shf[c] = f[((size_t)n * C + c) * HW + hw];
        __syncthreads();

        const float4* shf4 = (const float4*)shf;
        int C4 = C >> 2;
        for (int row = warp; row < LCH; row += 8) {
            const float4* wr = (const float4*)(w + (size_t)(a * LCH + row) * C);
            float acc = 0.f;
            for (int c4 = lane; c4 < C4; c4 += 32) {
                float4 wv = __ldg(wr + c4);
                float4 fv = shf4[c4];
                acc = fmaf(wv.x, fv.x, acc);
                acc = fmaf(wv.y, fv.y, acc);
                acc = fmaf(wv.z, fv.z, acc);
                acc = fmaf(wv.w, fv.w, acc);
            }
#pragma unroll
            for (int off = 16; off > 0; off >>= 1)
                acc += __shfl_xor_sync(0xFFFFFFFF, acc, off);
            if (lane == 0) lg[row] = acc + b[a * LCH + row];
        }
        __syncthreads();

        if (t == 0) {
            float px = sigf(lg[0]), py = sigf(lg[1]);
            float pw = sigf(lg[2]), ph = sigf(lg[3]);
            s_obj = sigf(lg[4]);
            int gx = hw % W, gy = hw / W;
            float2 anc = c_anchors[level][a];
            float cx = (2.f * px - 0.5f + (float)gx) * stride;
            float cy = (2.f * py - 0.5f + (float)gy) * stride;
            float bw = 4.f * pw * pw * anc.x;
            float bh = 4.f * ph * ph * anc.y;
            float x1 = cx - 0.5f * bw, y1 = cy - 0.5f * bh;
            float x2 = cx + 0.5f * bw, y2 = cy + 0.5f * bh;
            x1 = fminf(fmaxf(x1, 0.f), IMGF);
            y1 = fminf(fmaxf(y1, 0.f), IMGF);
            x2 = fminf(fmaxf(x2, 0.f), IMGF);
            y2 = fminf(fmaxf(y2, 0.f), IMGF);
            s_box = make_float4(x1, y1, x2, y2);
        }
        __syncthreads();

        if (t < NUM_CLASSES) {
            float ob = s_obj;
            if (ob > SCORE_T) {
                float s = ob * sigf(lg[5 + t]);
                if (s > SCORE_T) {
                    int pos = atomicAdd(&g_cnt[1 + n], 1);
                    if (pos < DCAP) {
                        g_detScore[n][pos] = s;
                        g_detBox[n][pos]   = s_box;
                        g_detInfo[n][pos]  = (aoff + hw * 3 + a) * NUM_CLASSES + t;
                    }
                }
            }
        }
        __syncthreads();
    }
}

// ------------- pass 3: adaptive sort + greedy NMS + output + counter reset -------------
__global__ void nms_kernel(const float* __restrict__ sf, float* __restrict__ out)
{
    extern __shared__ char smem[];
    unsigned long long* keys = (unsigned long long*)smem;
    int*    payload = (int*)   (smem + SORT_N * 8);
    float4* box     = (float4*)(smem + SORT_N * 12);
    float*  scr     = (float*) (smem + SORT_N * 12 + TOPK * 16);
    int*    lab     = (int*)   (smem + SORT_N * 12 + TOPK * 20);
    int*    val     = (int*)   (smem + SORT_N * 12 + TOPK * 24);
    __shared__ int picks[DET];
    __shared__ int s_sel, s_np;

    int n = blockIdx.x;
    int tid = threadIdx.x;
    int M = g_cnt[1 + n];
    if (M > DCAP) M = DCAP;
    if (tid == 0) s_np = 0;

    if (M > 0) {
        int sortN = 2;
        while (sortN < M) sortN <<= 1;

        for (int i = tid; i < sortN; i += blockDim.x) {
            if (i < M) {
                unsigned u = __float_as_uint(g_detScore[n][i]);
                u = (u & 0x80000000u) ? ~u : (u | 0x80000000u);
                keys[i] = ((unsigned long long)u << 32) | (unsigned)(0x7FFFFFFF - g_detInfo[n][i]);
                payload[i] = i;
            } else {
                keys[i] = 0ULL;
                payload[i] = -1;
            }
        }
        __syncthreads();

        for (int k = 2; k <= sortN; k <<= 1) {
            for (int j = k >> 1; j > 0; j >>= 1) {
                for (int i = tid; i < sortN; i += blockDim.x) {
                    int ixj = i ^ j;
                    if (ixj > i) {
                        bool up = ((i & k) == 0);
                        unsigned long long ka = keys[i], kb = keys[ixj];
                        bool sw = up ? (ka < kb) : (ka > kb);
                        if (sw) {
                            keys[i] = kb; keys[ixj] = ka;
                            int p = payload[i]; payload[i] = payload[ixj]; payload[ixj] = p;
                        }
                    }
                }
                __syncthreads();
            }
        }

        int M2 = M < TOPK ? M : TOPK;
        for (int i = tid; i < M2; i += blockDim.x) {
            int ci = payload[i];
            box[i] = g_detBox[n][ci];
            scr[i] = g_detScore[n][ci];
            lab[i] = g_detInfo[n][ci] % NUM_CLASSES;
            val[i] = 1;
        }
        __syncthreads();

        int cursor = 0;
        for (int iter = 0; iter < DET; iter++) {
            if (tid == 0) {
                int sel = -1;
                for (int j = cursor; j < M2; j++)
                    if (val[j]) { sel = j; break; }
                s_sel = sel;
                if (sel >= 0) {
                    picks[iter] = sel;
                    val[sel] = 0;
                    s_np = iter + 1;
                    cursor = sel + 1;
                }
            }
            __syncthreads();
            int sel = s_sel;
            if (sel < 0) break;
            float4 bs = box[sel];
            int ls = lab[sel];
            float areaS = (bs.z - bs.x) * (bs.w - bs.y);
            for (int j = tid; j < M2; j += blockDim.x) {
                if (val[j] && lab[j] == ls) {
                    float4 bj = box[j];
                    float ix1 = fmaxf(bs.x, bj.x), iy1 = fmaxf(bs.y, bj.y);
                    float ix2 = fminf(bs.z, bj.z), iy2 = fminf(bs.w, bj.w);
                    float iw = fmaxf(ix2 - ix1, 0.f), ih = fmaxf(iy2 - iy1, 0.f);
                    float inter = iw * ih;
                    float aj = (bj.z - bj.x) * (bj.w - bj.y);
                    float iou = inter / (areaS + aj - inter + 1e-7f);
                    if (iou > NMS_T) val[j] = 0;
                }
            }
            __syncthreads();
        }
        __syncthreads();
    }
    __syncthreads();

    int np = s_np;
    float s = sf[n];
    for (int d = tid; d < DET; d += blockDim.x) {
        float o0 = 0, o1 = 0, o2 = 0, o3 = 0, o4 = 0, o5 = 0;
        if (d < np) {
            int p = picks[d];
            float4 bbv = box[p];
            o0 = bbv.x / s; o1 = bbv.y / s; o2 = bbv.z / s; o3 = bbv.w / s;
            o4 = scr[p];
            o5 = (float)lab[p];
        }
        float* po = out + ((size_t)n * DET + d) * 6;
        po[0] = o0; po[1] = o1; po[2] = o2; po[3] = o3; po[4] = o4; po[5] = o5;
    }

    // reset counters for the next (graph-replayed) call
    __syncthreads();
    if (tid == 0) {
        g_cnt[1 + n] = 0;
        if (n == 0) g_cnt[0] = 0;
    }
}

// ---------------- launch ----------------
extern "C" void kernel_launch(void* const* d_in, const int* in_sizes, int n_in,
                              void* d_out, int out_size)
{
    const float *f0 = nullptr, *f1 = nullptr, *f2 = nullptr;
    const float *w0 = nullptr, *w1 = nullptr, *w2 = nullptr;
    const float *bbp[3] = {nullptr, nullptr, nullptr};
    const float *sf = nullptr;
    int bcount = 0;
    for (int i = 0; i < n_in; i++) {
        const float* p = (const float*)d_in[i];
        switch (in_sizes[i]) {
            case 6553600: f0 = p; break;
            case 3276800: f1 = p; break;
            case 1638400: f2 = p; break;
            case 32640:   w0 = p; break;
            case 65280:   w1 = p; break;
            case 130560:  w2 = p; break;
            case 255:     if (bcount < 3) bbp[bcount++] = p; break;
            case 8:       sf = p; break;
            default: break;
        }
    }
    const float *b0 = bbp[0], *b1 = bbp[1], *b2 = bbp[2];
    float* out = (float*)d_out;

    obj_kernel<<<OBJ_BLOCKS, 256>>>(f0, f1, f2, w0, w1, w2, b0, b1, b2);
    cand_kernel<<<320, 256>>>(f0, f1, f2, w0, w1, w2, b0, b1, b2);

    static int smem_set = 0;
    size_t nms_smem = SORT_N * 12 + TOPK * 28;
    if (!smem_set) {
        cudaFuncSetAttribute(nms_kernel, cudaFuncAttributeMaxDynamicSharedMemorySize, (int)nms_smem);
        smem_set = 1;
    }
    nms_kernel<<<NIMG, 256, nms_smem>>>(sf, out);
}